// round 13
// baseline (speedup 1.0000x reference)
#include <cuda_runtime.h>
#include <cuda_fp16.h>
#include <cuda_bf16.h>
#include <cstdint>

// Problem constants (shapes fixed by the dataset)
#define NMAX 50000
#define EMAX 1600000
#define KDIM 128          // inner dim of every GEMM (IN = H = 128)
#define HMAX 128
static __device__ __constant__ float c_eps = 1e-5f;

// ---------------- scratch (static device globals; no allocs allowed) -------
__device__ int    g_deg[NMAX];
__device__ int    g_rowptr[NMAX + 1];
__device__ int    g_cursor[NMAX];
__device__ int    g_csr[EMAX];
__device__ __half g_hl[NMAX * HMAX];      // fp16 messages (gathered by agg)
__device__ float  g_hr[NMAX * HMAX];
__device__ float  g_y [NMAX * HMAX];
__device__ float  g_sum[HMAX];
__device__ float  g_sq [HMAX];
__device__ float  g_scale[HMAX];
__device__ float  g_shift[HMAX];
// prepacked split-bf16 weights: slot i (0..5) at offset i*8192 words.
// slots: 0=Wl0 1=Wr0 2=Wl1 3=Wr1 4=Wl2 5=Wr2 ; row stride 64 words (K=128).
__device__ uint32_t g_pkh[6 * 8192];
__device__ uint32_t g_pkl[6 * 8192];

// ---------------- CSR construction -----------------------------------------
__global__ void k_zero(int n) {
    int i = blockIdx.x * blockDim.x + threadIdx.x;
    if (i < n) g_deg[i] = 0;
    if (i < HMAX) { g_sum[i] = 0.f; g_sq[i] = 0.f; }
}

// 4-edge batched histogram: 4 independent L2 atomics in flight per thread.
__global__ void k_hist(const int* __restrict__ dst, int e) {
    int i = (blockIdx.x * blockDim.x + threadIdx.x) * 4;
    if (i + 4 <= e) {
        int4 d = *(const int4*)(dst + i);
        atomicAdd(&g_deg[d.x], 1);
        atomicAdd(&g_deg[d.y], 1);
        atomicAdd(&g_deg[d.z], 1);
        atomicAdd(&g_deg[d.w], 1);
    } else {
        for (; i < e; i++) atomicAdd(&g_deg[dst[i]], 1);
    }
}

// single-block exclusive scan over g_deg -> g_rowptr (and g_cursor).
__global__ void k_scan(int n) {
    __shared__ int wsum[32];
    __shared__ int carry_s;
    const int t = threadIdx.x;
    const int lane = t & 31;
    const int wid  = t >> 5;
    if (t == 0) carry_s = 0;
    __syncthreads();
    for (int base = 0; base < n; base += 1024) {
        int v = (base + t < n) ? g_deg[base + t] : 0;
        int val = v;
#pragma unroll
        for (int off = 1; off < 32; off <<= 1) {
            int x = __shfl_up_sync(0xffffffffu, val, off);
            if (lane >= off) val += x;
        }
        if (lane == 31) wsum[wid] = val;
        __syncthreads();
        if (wid == 0) {
            int s = wsum[lane];
#pragma unroll
            for (int off = 1; off < 32; off <<= 1) {
                int x = __shfl_up_sync(0xffffffffu, s, off);
                if (lane >= off) s += x;
            }
            wsum[lane] = s;
        }
        __syncthreads();
        int prefix = (wid > 0) ? wsum[wid - 1] : 0;
        int incl   = val + prefix;
        int carry  = carry_s;
        if (base + t < n) {
            int ex = carry + incl - v;
            g_rowptr[base + t] = ex;
            g_cursor[base + t] = ex;
        }
        __syncthreads();
        if (t == 1023) carry_s = carry + incl;
        __syncthreads();
    }
    if (t == 0) g_rowptr[n] = carry_s;
}

// 4-edge batched fill.
__global__ void k_fill(const int* __restrict__ src, const int* __restrict__ dst, int e) {
    int i = (blockIdx.x * blockDim.x + threadIdx.x) * 4;
    if (i + 4 <= e) {
        int4 d = *(const int4*)(dst + i);
        int4 s = *(const int4*)(src + i);
        int p0 = atomicAdd(&g_cursor[d.x], 1);
        int p1 = atomicAdd(&g_cursor[d.y], 1);
        int p2 = atomicAdd(&g_cursor[d.z], 1);
        int p3 = atomicAdd(&g_cursor[d.w], 1);
        g_csr[p0] = s.x; g_csr[p1] = s.y; g_csr[p2] = s.z; g_csr[p3] = s.w;
    } else {
        for (; i < e; i++) {
            int p = atomicAdd(&g_cursor[dst[i]], 1);
            g_csr[p] = src[i];
        }
    }
}

// ---------------- split-bf16 helpers ---------------------------------------
__device__ __forceinline__ uint32_t pack2_bf16(float a, float b) {
    __nv_bfloat162 h = __floats2bfloat162_rn(a, b);
    return *reinterpret_cast<uint32_t*>(&h);
}

__device__ __forceinline__ void split2(float f0, float f1, uint32_t& hi, uint32_t& lo) {
    __nv_bfloat16 h0 = __float2bfloat16_rn(f0);
    __nv_bfloat16 h1 = __float2bfloat16_rn(f1);
    float l0 = f0 - __bfloat162float(h0);
    float l1 = f1 - __bfloat162float(h1);
    __nv_bfloat162 hh; hh.x = h0; hh.y = h1;
    hi = *reinterpret_cast<uint32_t*>(&hh);
    lo = pack2_bf16(l0, l1);
}

__device__ __forceinline__ void mma_bf16(float* c, const uint32_t* a, const uint32_t* b) {
    asm volatile(
        "mma.sync.aligned.m16n8k16.row.col.f32.bf16.bf16.f32 "
        "{%0,%1,%2,%3}, {%4,%5,%6,%7}, {%8,%9}, {%0,%1,%2,%3};\n"
        : "+f"(c[0]), "+f"(c[1]), "+f"(c[2]), "+f"(c[3])
        : "r"(a[0]), "r"(a[1]), "r"(a[2]), "r"(a[3]),
          "r"(b[0]), "r"(b[1]));
}

// ---------------- weight pre-pack: fp32 W -> split-bf16 hi/lo ---------------
__global__ void k_pack(const float* __restrict__ W, int slot, int words) {
    int i = blockIdx.x * blockDim.x + threadIdx.x;
    if (i < words) {
        float2 f = *(const float2*)(W + 2 * i);
        uint32_t hi, lo;
        split2(f.x, f.y, hi, lo);
        g_pkh[slot * 8192 + i] = hi;
        g_pkl[slot * 8192 + i] = lo;
    }
}

// ---------------- fused dual GEMM (tensor cores, split-bf16) ----------------
// hl16 = fp16( act(X) @ Wl^T ) ; hr = act(X) @ Wr^T + bias  (fp32)
// act(x) = relu(x*scale[k] + shift[k]) when scale != null.
// Weights arrive pre-packed (hi/lo bf16 pairs); only X is converted in-kernel.
template <int HOUT>
__global__ void __launch_bounds__(256)
k_gemm2(const float* __restrict__ X,
        const uint32_t* __restrict__ pWlh, const uint32_t* __restrict__ pWll,
        const uint32_t* __restrict__ pWrh, const uint32_t* __restrict__ pWrl,
        const float* __restrict__ bias,
        const float* __restrict__ scale, const float* __restrict__ shift,
        __half* __restrict__ hl16, float* __restrict__ hr, int n)
{
    constexpr int NT = HOUT / 8;          // n-tiles per warp (16 or 8)
    constexpr int RS = 9;                 // row stride in u32 words (16 bf16 + pad)
    __shared__ uint32_t sXh[128 * RS], sXl[128 * RS];
    __shared__ uint32_t sWlh[HOUT * RS], sWll[HOUT * RS];
    __shared__ uint32_t sWrh[HOUT * RS], sWrl[HOUT * RS];

    const int t    = threadIdx.x;
    const int lane = t & 31;
    const int w    = t >> 5;              // warp 0..7
    const int g    = lane >> 2;           // group 0..7
    const int tig  = lane & 3;            // thread-in-group 0..3
    const int r0   = blockIdx.x * 128;

    float accL[NT][4], accR[NT][4];
#pragma unroll
    for (int j = 0; j < NT; j++)
#pragma unroll
        for (int q = 0; q < 4; q++) { accL[j][q] = 0.f; accR[j][q] = 0.f; }

    // loader coordinates
    const int xrow = t >> 1;              // 0..127
    const int xseg = t & 1;               // 0/1: cols [seg*8, seg*8+8)
    const int wmat = t / HOUT;            // 0 = Wl, 1 = Wr (only t < 2*HOUT active)
    const int wrow = t % HOUT;

    for (int k0 = 0; k0 < KDIM; k0 += 16) {
        // ---- X tile: 128 x 16 fp32 -> BN/ReLU -> split bf16 hi/lo
        {
            int gr = r0 + xrow;
            float f[8];
            if (gr < n) {
                const float* xp = X + (size_t)gr * KDIM + k0 + xseg * 8;
                float4 v1 = *(const float4*)(xp);
                float4 v2 = *(const float4*)(xp + 4);
                f[0]=v1.x; f[1]=v1.y; f[2]=v1.z; f[3]=v1.w;
                f[4]=v2.x; f[5]=v2.y; f[6]=v2.z; f[7]=v2.w;
            } else {
#pragma unroll
                for (int i = 0; i < 8; i++) f[i] = 0.f;
            }
            if (scale) {
                int kb = k0 + xseg * 8;
#pragma unroll
                for (int i = 0; i < 8; i++)
                    f[i] = fmaxf(0.f, f[i] * scale[kb + i] + shift[kb + i]);
            }
            int base = xrow * RS + xseg * 4;
#pragma unroll
            for (int p = 0; p < 4; p++) {
                uint32_t hi, lo;
                split2(f[2*p], f[2*p+1], hi, lo);
                sXh[base + p] = hi;
                sXl[base + p] = lo;
            }
        }
        // ---- W tiles: prepacked hi/lo straight to smem
        if (t < 2 * HOUT) {
            const uint32_t* ph = (wmat ? pWrh : pWlh) + wrow * 64 + (k0 >> 1);
            const uint32_t* pl = (wmat ? pWrl : pWll) + wrow * 64 + (k0 >> 1);
            uint4 h1 = *(const uint4*)(ph);
            uint4 h2 = *(const uint4*)(ph + 4);
            uint4 l1 = *(const uint4*)(pl);
            uint4 l2 = *(const uint4*)(pl + 4);
            uint32_t* dh = wmat ? sWrh : sWlh;
            uint32_t* dl = wmat ? sWrl : sWll;
            int base = wrow * RS;
            dh[base+0]=h1.x; dh[base+1]=h1.y; dh[base+2]=h1.z; dh[base+3]=h1.w;
            dh[base+4]=h2.x; dh[base+5]=h2.y; dh[base+6]=h2.z; dh[base+7]=h2.w;
            dl[base+0]=l1.x; dl[base+1]=l1.y; dl[base+2]=l1.z; dl[base+3]=l1.w;
            dl[base+4]=l2.x; dl[base+5]=l2.y; dl[base+6]=l2.z; dl[base+7]=l2.w;
        }
        __syncthreads();

        // ---- mma: each warp does rows [w*16, w*16+16) x all HOUT cols
        uint32_t ah[4], al[4];
        {
            int ra = (w * 16 + g) * RS;
            int rb = (w * 16 + g + 8) * RS;
            ah[0] = sXh[ra + tig];     ah[1] = sXh[rb + tig];
            ah[2] = sXh[ra + tig + 4]; ah[3] = sXh[rb + tig + 4];
            al[0] = sXl[ra + tig];     al[1] = sXl[rb + tig];
            al[2] = sXl[ra + tig + 4]; al[3] = sXl[rb + tig + 4];
        }
#pragma unroll
        for (int j = 0; j < NT; j++) {
            int rb = (j * 8 + g) * RS + tig;
            uint32_t bh[2], bl[2];
            bh[0] = sWlh[rb]; bh[1] = sWlh[rb + 4];
            bl[0] = sWll[rb]; bl[1] = sWll[rb + 4];
            mma_bf16(accL[j], ah, bh);
            mma_bf16(accL[j], ah, bl);
            mma_bf16(accL[j], al, bh);
            bh[0] = sWrh[rb]; bh[1] = sWrh[rb + 4];
            bl[0] = sWrl[rb]; bl[1] = sWrl[rb + 4];
            mma_bf16(accR[j], ah, bh);
            mma_bf16(accR[j], ah, bl);
            mma_bf16(accR[j], al, bh);
        }
        __syncthreads();
    }

    // ---- epilogue: C frag (r=g / g+8, c=2*tig, 2*tig+1)
    {
        int rowA = r0 + w * 16 + g;
        int rowB = rowA + 8;
#pragma unroll
        for (int j = 0; j < NT; j++) {
            int c = j * 8 + 2 * tig;
            float b0 = bias[c], b1 = bias[c + 1];
            if (rowA < n) {
                *(__half2*)(hl16 + (size_t)rowA * HOUT + c) =
                    __floats2half2_rn(accL[j][0], accL[j][1]);
                *(float2*)(hr + (size_t)rowA * HOUT + c) =
                    make_float2(accR[j][0] + b0, accR[j][1] + b1);
            }
            if (rowB < n) {
                *(__half2*)(hl16 + (size_t)rowB * HOUT + c) =
                    __floats2half2_rn(accL[j][2], accL[j][3]);
                *(float2*)(hr + (size_t)rowB * HOUT + c) =
                    make_float2(accR[j][2] + b0, accR[j][3] + b1);
            }
        }
    }
}

// ---------------- aggregation: y = mean_nbr(hl16) + hr ----------------------
template <int HC, bool STATS>
__global__ void __launch_bounds__(512)
k_agg(const __half* __restrict__ hl16, const float* __restrict__ hr,
      float* __restrict__ y, int n)
{
    constexpr int VEC = HC / 32;   // 4 or 2 halves per lane per row
    __shared__ float ssum[HC];
    __shared__ float ssq [HC];
    const int t    = threadIdx.x;
    const int lane = t & 31;
    const int w    = t >> 5;

    if (STATS) {
        if (t < HC) { ssum[t] = 0.f; ssq[t] = 0.f; }
        __syncthreads();
    }

    int node = blockIdx.x * 16 + w;
    if (node < n) {
        int beg = g_rowptr[node];
        int end = g_rowptr[node + 1];
        const __half* base = hl16 + lane * VEC;

        float a0 = 0.f, a1 = 0.f, a2 = 0.f, a3 = 0.f;
        int e = beg;

        if (VEC == 4) {
            for (; e + 8 <= end; e += 8) {
                uint2 r[8];
#pragma unroll
                for (int q = 0; q < 8; q++) {
                    int j = g_csr[e + q];
                    r[q] = *(const uint2*)(base + (size_t)j * HC);
                }
#pragma unroll
                for (int q = 0; q < 8; q++) {
                    float2 f0 = __half22float2(*(__half2*)&r[q].x);
                    float2 f1 = __half22float2(*(__half2*)&r[q].y);
                    a0 += f0.x; a1 += f0.y; a2 += f1.x; a3 += f1.y;
                }
            }
            for (; e + 4 <= end; e += 4) {
                uint2 r[4];
#pragma unroll
                for (int q = 0; q < 4; q++) {
                    int j = g_csr[e + q];
                    r[q] = *(const uint2*)(base + (size_t)j * HC);
                }
#pragma unroll
                for (int q = 0; q < 4; q++) {
                    float2 f0 = __half22float2(*(__half2*)&r[q].x);
                    float2 f1 = __half22float2(*(__half2*)&r[q].y);
                    a0 += f0.x; a1 += f0.y; a2 += f1.x; a3 += f1.y;
                }
            }
            for (; e < end; e++) {
                int j = g_csr[e];
                uint2 rr = *(const uint2*)(base + (size_t)j * HC);
                float2 f0 = __half22float2(*(__half2*)&rr.x);
                float2 f1 = __half22float2(*(__half2*)&rr.y);
                a0 += f0.x; a1 += f0.y; a2 += f1.x; a3 += f1.y;
            }
        } else {
            for (; e + 8 <= end; e += 8) {
                unsigned r[8];
#pragma unroll
                for (int q = 0; q < 8; q++) {
                    int j = g_csr[e + q];
                    r[q] = *(const unsigned*)(base + (size_t)j * HC);
                }
#pragma unroll
                for (int q = 0; q < 8; q++) {
                    float2 f = __half22float2(*(__half2*)&r[q]);
                    a0 += f.x; a1 += f.y;
                }
            }
            for (; e + 4 <= end; e += 4) {
                unsigned r[4];
#pragma unroll
                for (int q = 0; q < 4; q++) {
                    int j = g_csr[e + q];
                    r[q] = *(const unsigned*)(base + (size_t)j * HC);
                }
#pragma unroll
                for (int q = 0; q < 4; q++) {
                    float2 f = __half22float2(*(__half2*)&r[q]);
                    a0 += f.x; a1 += f.y;
                }
            }
            for (; e < end; e++) {
                int j = g_csr[e];
                unsigned rr = *(const unsigned*)(base + (size_t)j * HC);
                float2 f = __half22float2(*(__half2*)&rr);
                a0 += f.x; a1 += f.y;
            }
        }

        float dinv = 1.f / (float)max(end - beg, 1);
        const float* hrp = hr + (size_t)node * HC + lane * VEC;
        float* yp = y + (size_t)node * HC + lane * VEC;
        float v[4];
        v[0] = a0 * dinv + hrp[0];
        v[1] = a1 * dinv + hrp[1];
        if (VEC == 4) {
            v[2] = a2 * dinv + hrp[2];
            v[3] = a3 * dinv + hrp[3];
            *(float4*)yp = make_float4(v[0], v[1], v[2], v[3]);
        } else {
            *(float2*)yp = make_float2(v[0], v[1]);
        }
        if (STATS) {
#pragma unroll
            for (int i = 0; i < VEC; i++) {
                atomicAdd(&ssum[lane * VEC + i], v[i]);
                atomicAdd(&ssq [lane * VEC + i], v[i] * v[i]);
            }
        }
    }

    if (STATS) {
        __syncthreads();
        if (t < HC) {
            atomicAdd(&g_sum[t], ssum[t]);
            atomicAdd(&g_sq [t], ssq [t]);
        }
    }
}

// ---------------- BN finalize: scale/shift from accumulated stats ----------
__global__ void k_bnfin(const float* __restrict__ gamma,
                        const float* __restrict__ beta, int n)
{
    int c = threadIdx.x;
    if (c < HMAX) {
        float inv_n = 1.f / (float)n;
        float mu  = g_sum[c] * inv_n;
        float var = fmaxf(g_sq[c] * inv_n - mu * mu, 0.f);
        float s   = gamma[c] * rsqrtf(var + c_eps);
        g_scale[c] = s;
        g_shift[c] = beta[c] - mu * s;
        g_sum[c] = 0.f;
        g_sq [c] = 0.f;
    }
}

// ---------------- driver ----------------------------------------------------
extern "C" void kernel_launch(void* const* d_in, const int* in_sizes, int n_in,
                              void* d_out, int out_size)
{
    const float* x   = (const float*)d_in[0];
    const int*   ei  = (const int*)  d_in[1];
    const float* Wl0 = (const float*)d_in[2];
    const float* Wr0 = (const float*)d_in[3];
    const float* b0  = (const float*)d_in[4];
    const float* g0  = (const float*)d_in[5];
    const float* be0 = (const float*)d_in[6];
    const float* Wl1 = (const float*)d_in[7];
    const float* Wr1 = (const float*)d_in[8];
    const float* b1  = (const float*)d_in[9];
    const float* g1  = (const float*)d_in[10];
    const float* be1 = (const float*)d_in[11];
    const float* Wl2 = (const float*)d_in[12];
    const float* Wr2 = (const float*)d_in[13];
    const float* b2  = (const float*)d_in[14];

    const int n = in_sizes[0] / KDIM;
    const int e = in_sizes[1] / 2;
    const int* src = ei;
    const int* dst = ei + e;

    __half* hl;
    float *hr, *y, *scale, *shift;
    uint32_t *pkh, *pkl;
    cudaGetSymbolAddress((void**)&hl,    g_hl);
    cudaGetSymbolAddress((void**)&hr,    g_hr);
    cudaGetSymbolAddress((void**)&y,     g_y);
    cudaGetSymbolAddress((void**)&scale, g_scale);
    cudaGetSymbolAddress((void**)&shift, g_shift);
    cudaGetSymbolAddress((void**)&pkh,   g_pkh);
    cudaGetSymbolAddress((void**)&pkl,   g_pkl);

    // CSR build + weight pre-pack
    k_zero<<<(n + 255) / 256, 256>>>(n);
    k_hist<<<(e / 4 + 511) / 512, 512>>>(dst, e);
    k_pack<<<32, 256>>>(Wl0, 0, 8192);
    k_pack<<<32, 256>>>(Wr0, 1, 8192);
    k_pack<<<32, 256>>>(Wl1, 2, 8192);
    k_pack<<<32, 256>>>(Wr1, 3, 8192);
    k_pack<<<16, 256>>>(Wl2, 4, 4096);
    k_pack<<<16, 256>>>(Wr2, 5, 4096);
    k_scan<<<1, 1024>>>(n);
    k_fill<<<(e / 4 + 511) / 512, 512>>>(src, dst, e);

    const int gb = (n + 127) / 128;     // GEMM blocks (128 rows each)
    const int ab = (n + 15) / 16;       // agg blocks (16 nodes each)

    // layer 0: SAGEConv(128->128) + BN + ReLU (BN+ReLU deferred to next load)
    k_gemm2<128><<<gb, 256>>>(x, pkh + 0*8192, pkl + 0*8192, pkh + 1*8192, pkl + 1*8192,
                              b0, nullptr, nullptr, hl, hr, n);
    k_agg<128, true><<<ab, 512>>>(hl, hr, y, n);
    k_bnfin<<<1, 128>>>(g0, be0, n);

    // layer 1
    k_gemm2<128><<<gb, 256>>>(y, pkh + 2*8192, pkl + 2*8192, pkh + 3*8192, pkl + 3*8192,
                              b1, scale, shift, hl, hr, n);
    k_agg<128, true><<<ab, 512>>>(hl, hr, y, n);
    k_bnfin<<<1, 128>>>(g1, be1, n);

    // layer 2: SAGEConv(128->64), no BN
    k_gemm2<64><<<gb, 256>>>(y, pkh + 4*8192, pkl + 4*8192, pkh + 5*8192, pkl + 5*8192,
                             b2, scale, shift, hl, hr, n);
    k_agg<64, false><<<ab, 512>>>(hl, hr, (float*)d_out, n);
}